// round 14
// baseline (speedup 1.0000x reference)
#include <cuda_runtime.h>
#include <cuda_fp16.h>
#include <cstdint>
#include <math.h>

typedef __half h16;
typedef unsigned int u32;

#define BB 2
#define SQ 2048
#define DM 1024
#define NHD 16
#define FF 4096
#define MR (BB*SQ)

// ------------------- scratch (device globals) -------------------
__device__ h16 s_xq[MR*DM];
__device__ h16 s_xk[MR*DM];
__device__ h16 s_wq[DM*DM];
__device__ h16 s_wk[DM*DM];
__device__ h16 s_wv[DM*DM];
__device__ h16 s_wo[DM*DM];
__device__ h16 s_w1[FF*DM];
__device__ h16 s_w2[DM*FF];
__device__ h16 s_q[MR*DM];
__device__ h16 s_k[MR*DM];
__device__ h16 s_v[MR*DM];
__device__ h16 s_o[MR*DM];
__device__ float s_x1[MR*DM];
__device__ h16 s_ln[MR*DM];
__device__ h16 s_h[(size_t)MR*FF];
__device__ float s_x2[MR*DM];

// ------------------- helpers -------------------
__device__ __forceinline__ u32 smem_u32(const void* p) {
    return (u32)__cvta_generic_to_shared(p);
}
#define CP16(dst, src) \
    asm volatile("cp.async.cg.shared.global [%0], [%1], 16;" :: "r"(dst), "l"(src))
#define CP_COMMIT() asm volatile("cp.async.commit_group;" ::: "memory")
#define CP_WAIT1()  asm volatile("cp.async.wait_group 1;" ::: "memory")
#define CP_WAIT0()  asm volatile("cp.async.wait_group 0;" ::: "memory")

#define LDSM4(r0, r1, r2, r3, addr) \
    asm volatile("ldmatrix.sync.aligned.m8n8.x4.shared.b16 {%0,%1,%2,%3}, [%4];" \
        : "=r"(r0), "=r"(r1), "=r"(r2), "=r"(r3) : "r"(addr))
#define LDSM4T(r0, r1, r2, r3, addr) \
    asm volatile("ldmatrix.sync.aligned.m8n8.x4.trans.shared.b16 {%0,%1,%2,%3}, [%4];" \
        : "=r"(r0), "=r"(r1), "=r"(r2), "=r"(r3) : "r"(addr))

__device__ __forceinline__ void mma_f16(float* c, const u32* a, const u32* b) {
    asm volatile("mma.sync.aligned.m16n8k16.row.col.f32.f16.f16.f32 "
        "{%0,%1,%2,%3}, {%4,%5,%6,%7}, {%8,%9}, {%0,%1,%2,%3};"
        : "+f"(c[0]), "+f"(c[1]), "+f"(c[2]), "+f"(c[3])
        : "r"(a[0]), "r"(a[1]), "r"(a[2]), "r"(a[3]), "r"(b[0]), "r"(b[1]));
}

__device__ __forceinline__ u32 pack2(h16 a, h16 b) {
    return (u32)__half_as_ushort(a) | ((u32)__half_as_ushort(b) << 16);
}
__device__ __forceinline__ u32 pack2f(float a, float b) {
    return pack2(__float2half_rn(a), __float2half_rn(b));
}

// ===================================================================
// GEMM config: BM=BN=128, BK=32, 128 thr, 2x2 warps, warp tile 64x64.
// A, B single fp16. 3-stage cp.async pipeline, 61.4KB smem -> 3 CTAs/SM.
// ===================================================================
#define G_ROWB  80u
#define G_B_OFF (128u * G_ROWB)
#define G_STG   (2u * 128u * G_ROWB)   // 20480 per stage

// ------------------- HMMA GEMM (generic) -------------------
// C[m,n] = alpha * sum_k A[m,k]*B[n,k] (+ epilogue)
// EPI: 0 none; 1 +addM; 2 +biasN then GELU; 3 +addM +biasN
// OUTM: 0 -> fp32 C; 1 -> fp16 Ch
template<int EPI, int OUTM>
__global__ __launch_bounds__(128, 3)
void gemm_mma(const h16* __restrict__ Ah, const h16* __restrict__ Bh,
              float* __restrict__ C, h16* __restrict__ Ch,
              int K, int lda, int ldb, int ldc,
              float alpha,
              const float* __restrict__ addM, int ldadd,
              const float* __restrict__ biasN)
{
    extern __shared__ char smem[];
    const u32 sbase = smem_u32(smem);
    const int tid = threadIdx.x, lane = tid & 31, wid = tid >> 5;
    const int wm = wid & 1, wn = wid >> 1;

    const int m0 = blockIdx.y * 128, n0 = blockIdx.x * 128;

    float acc[4][8][4];
    #pragma unroll
    for (int i = 0; i < 4; i++)
        #pragma unroll
        for (int j = 0; j < 8; j++)
            #pragma unroll
            for (int t = 0; t < 4; t++) acc[i][j][t] = 0.0f;

    auto load_chunk = [&](int ck, int st) {
        const int k0 = ck * 32;
        const u32 sa = sbase + (u32)st * G_STG;
        #pragma unroll
        for (int it = 0; it < 4; it++) {
            int a = tid + it * 128;
            int row = a >> 2, ch = a & 3;
            u32 dst = sa + (u32)row * G_ROWB + (u32)ch * 16;
            CP16(dst,           Ah + (size_t)(m0 + row) * lda + k0 + ch * 8);
            CP16(dst + G_B_OFF, Bh + (size_t)(n0 + row) * ldb + k0 + ch * 8);
        }
    };

    auto compute = [&](int st) {
        const u32 ab  = sbase + (u32)st * G_STG;
        const u32 bb  = ab + G_B_OFF;
        const u32 rb  = (u32)((lane & 15) * G_ROWB);
        #pragma unroll
        for (int s16 = 0; s16 < 2; s16++) {
            const u32 coff = (u32)(s16 * 32 + (lane >> 4) * 16);
            u32 bh[8][2];
            #pragma unroll
            for (int np = 0; np < 4; np++) {
                u32 bd = bb + (u32)((wn * 64 + np * 16) * G_ROWB) + rb + coff;
                u32 t0, t1, t2, t3;
                LDSM4(t0, t1, t2, t3, bd);
                bh[2*np][0] = t0; bh[2*np+1][0] = t1; bh[2*np][1] = t2; bh[2*np+1][1] = t3;
            }
            #pragma unroll
            for (int mt = 0; mt < 4; mt++) {
                u32 ah[4];
                u32 ad = ab + (u32)((wm * 64 + mt * 16) * G_ROWB) + rb + coff;
                LDSM4(ah[0], ah[1], ah[2], ah[3], ad);
                #pragma unroll
                for (int nt = 0; nt < 8; nt++)
                    mma_f16(acc[mt][nt], ah, bh[nt]);
            }
        }
    };

    const int NC = K >> 5;
    load_chunk(0, 0); CP_COMMIT();
    load_chunk(1, 1); CP_COMMIT();
    for (int i = 0; i < NC; i++) {
        if (i + 1 < NC) CP_WAIT1(); else CP_WAIT0();
        __syncthreads();
        if (i + 2 < NC) { load_chunk(i + 2, (i + 2) % 3); CP_COMMIT(); }
        compute(i % 3);
    }

    auto proc2 = [&](int gm, int gn, float v0, float v1) {
        v0 *= alpha; v1 *= alpha;
        if (EPI == 1 || EPI == 3) {
            float2 ad = *(const float2*)(addM + (size_t)gm * ldadd + gn);
            v0 += ad.x; v1 += ad.y;
        }
        if (EPI == 2 || EPI == 3) {
            float2 bn2 = *(const float2*)(biasN + gn);
            v0 += bn2.x; v1 += bn2.y;
        }
        if (EPI == 2) {
            v0 = 0.5f * v0 * (1.0f + erff(v0 * 0.70710678118654752f));
            v1 = 0.5f * v1 * (1.0f + erff(v1 * 0.70710678118654752f));
        }
        if (OUTM == 0) {
            *(float2*)(C + (size_t)gm * ldc + gn) = make_float2(v0, v1);
        } else {
            *(u32*)(Ch + (size_t)gm * ldc + gn) = pack2f(v0, v1);
        }
    };

    const int r  = lane >> 2;
    const int c2 = (lane & 3) * 2;
    #pragma unroll
    for (int mt = 0; mt < 4; mt++) {
        #pragma unroll
        for (int nt = 0; nt < 8; nt++) {
            int gm = m0 + wm * 64 + mt * 16 + r;
            int gn = n0 + wn * 64 + nt * 8 + c2;
            proc2(gm,     gn, acc[mt][nt][0], acc[mt][nt][1]);
            proc2(gm + 8, gn, acc[mt][nt][2], acc[mt][nt][3]);
        }
    }
}

// ------------------- batched QKV GEMM (z selects matrix triple) -------------------
struct QKVArgs {
    const h16* Ah[3];
    const h16* Bh[3];
    h16* Ch[3];
};

__global__ __launch_bounds__(128, 3)
void gemm_qkv(QKVArgs args)
{
    extern __shared__ char smem[];
    const u32 sbase = smem_u32(smem);
    const int tid = threadIdx.x, lane = tid & 31, wid = tid >> 5;
    const int wm = wid & 1, wn = wid >> 1;
    const int zz = blockIdx.z;

    const h16* __restrict__ Ah = args.Ah[zz];
    const h16* __restrict__ Bh = args.Bh[zz];
    h16* __restrict__ Ch = args.Ch[zz];

    const int m0 = blockIdx.y * 128, n0 = blockIdx.x * 128;

    float acc[4][8][4];
    #pragma unroll
    for (int i = 0; i < 4; i++)
        #pragma unroll
        for (int j = 0; j < 8; j++)
            #pragma unroll
            for (int t = 0; t < 4; t++) acc[i][j][t] = 0.0f;

    auto load_chunk = [&](int ck, int st) {
        const int k0 = ck * 32;
        const u32 sa = sbase + (u32)st * G_STG;
        #pragma unroll
        for (int it = 0; it < 4; it++) {
            int a = tid + it * 128;
            int row = a >> 2, ch = a & 3;
            u32 dst = sa + (u32)row * G_ROWB + (u32)ch * 16;
            CP16(dst,           Ah + (size_t)(m0 + row) * DM + k0 + ch * 8);
            CP16(dst + G_B_OFF, Bh + (size_t)(n0 + row) * DM + k0 + ch * 8);
        }
    };

    auto compute = [&](int st) {
        const u32 ab  = sbase + (u32)st * G_STG;
        const u32 bb  = ab + G_B_OFF;
        const u32 rb  = (u32)((lane & 15) * G_ROWB);
        #pragma unroll
        for (int s16 = 0; s16 < 2; s16++) {
            const u32 coff = (u32)(s16 * 32 + (lane >> 4) * 16);
            u32 bh[8][2];
            #pragma unroll
            for (int np = 0; np < 4; np++) {
                u32 bd = bb + (u32)((wn * 64 + np * 16) * G_ROWB) + rb + coff;
                u32 t0, t1, t2, t3;
                LDSM4(t0, t1, t2, t3, bd);
                bh[2*np][0] = t0; bh[2*np+1][0] = t1; bh[2*np][1] = t2; bh[2*np+1][1] = t3;
            }
            #pragma unroll
            for (int mt = 0; mt < 4; mt++) {
                u32 ah[4];
                u32 ad = ab + (u32)((wm * 64 + mt * 16) * G_ROWB) + rb + coff;
                LDSM4(ah[0], ah[1], ah[2], ah[3], ad);
                #pragma unroll
                for (int nt = 0; nt < 8; nt++)
                    mma_f16(acc[mt][nt], ah, bh[nt]);
            }
        }
    };

    const int NC = DM >> 5;
    load_chunk(0, 0); CP_COMMIT();
    load_chunk(1, 1); CP_COMMIT();
    for (int i = 0; i < NC; i++) {
        if (i + 1 < NC) CP_WAIT1(); else CP_WAIT0();
        __syncthreads();
        if (i + 2 < NC) { load_chunk(i + 2, (i + 2) % 3); CP_COMMIT(); }
        compute(i % 3);
    }

    const int r  = lane >> 2;
    const int c2 = (lane & 3) * 2;
    #pragma unroll
    for (int mt = 0; mt < 4; mt++) {
        #pragma unroll
        for (int nt = 0; nt < 8; nt++) {
            int gm = m0 + wm * 64 + mt * 16 + r;
            int gn = n0 + wn * 64 + nt * 8 + c2;
            *(u32*)(Ch + (size_t)gm * DM + gn)       = pack2f(acc[mt][nt][0], acc[mt][nt][1]);
            *(u32*)(Ch + (size_t)(gm + 8) * DM + gn) = pack2f(acc[mt][nt][2], acc[mt][nt][3]);
        }
    }
}

// ------------------- fused flash attention (all single fp16) -------------------
__global__ __launch_bounds__(256, 1)
void flash_k(const h16* __restrict__ qg,
             const h16* __restrict__ kh, const h16* __restrict__ vh,
             const float* __restrict__ bias,
             h16* __restrict__ og)
{
    constexpr u32 ROWB = 144;
    constexpr u32 HKV  = 64 * ROWB;
    constexpr u32 STG  = 2 * HKV;

    extern __shared__ char smem[];
    const u32 sbase = smem_u32(smem);
    const int tid = threadIdx.x, lane = tid & 31, wid = tid >> 5;
    const int b = blockIdx.z, h = blockIdx.y, q0 = blockIdx.x * 128;

    const size_t qbase = ((size_t)b * SQ + q0) * DM + h * 64;
    const size_t kvbase = (size_t)b * SQ * DM + h * 64;
    const float* bptr = bias + ((size_t)(b * NHD + h)) * SQ * SQ;

    #pragma unroll
    for (int it = 0; it < 4; it++) {
        int idx = tid + it * 256;
        int row = idx >> 3, c8 = idx & 7;
        u32 dst = sbase + (u32)row * ROWB + (u32)c8 * 16;
        CP16(dst, qg + qbase + (size_t)row * DM + c8 * 8);
    }
    CP_COMMIT(); CP_WAIT0();
    __syncthreads();

    u32 qf[4][4];
    {
        const u32 base = sbase + (u32)((wid * 16 + (lane & 15)) * ROWB);
        #pragma unroll
        for (int kq = 0; kq < 4; kq++) {
            u32 ad = base + (u32)(kq * 32 + (lane >> 4) * 16);
            LDSM4(qf[kq][0], qf[kq][1], qf[kq][2], qf[kq][3], ad);
        }
    }
    __syncthreads();

    auto load_kv = [&](int ck, u32 st) {
        const int kv0 = ck * 64;
        #pragma unroll
        for (int it = 0; it < 2; it++) {
            int idx = tid + it * 256;
            int row = idx >> 3, c8 = idx & 7;
            size_t g = kvbase + (size_t)(kv0 + row) * DM + c8 * 8;
            u32 dst = st + (u32)row * ROWB + (u32)c8 * 16;
            CP16(dst,       kh + g);
            CP16(dst + HKV, vh + g);
        }
    };

    float o[8][4];
    #pragma unroll
    for (int d = 0; d < 8; d++)
        #pragma unroll
        for (int t = 0; t < 4; t++) o[d][t] = 0.0f;
    float rm0 = -1e30f, rm1 = -1e30f, rs0 = 0.0f, rs1 = 0.0f;

    load_kv(0, sbase); CP_COMMIT();

    const u32 rbA = (u32)((lane & 15) * ROWB);
    const int g4  = lane >> 2, t4 = lane & 3;

    for (int ck = 0; ck < SQ / 64; ck++) {
        const u32 st = sbase + (u32)(ck & 1) * STG;
        CP_WAIT0();
        __syncthreads();
        if (ck + 1 < SQ / 64) { load_kv(ck + 1, sbase + (u32)((ck + 1) & 1) * STG); CP_COMMIT(); }

        float S[8][4];
        #pragma unroll
        for (int j = 0; j < 8; j++)
            #pragma unroll
            for (int t = 0; t < 4; t++) S[j][t] = 0.0f;

        #pragma unroll
        for (int kq = 0; kq < 4; kq++) {
            const u32 coff = (u32)(kq * 32 + (lane >> 4) * 16);
            #pragma unroll
            for (int jp = 0; jp < 4; jp++) {
                u32 kd = st + (u32)(jp * 16 * ROWB) + rbA + coff;
                u32 t0, t1, t2, t3;
                u32 bh[2][2];
                LDSM4(t0, t1, t2, t3, kd);
                bh[0][0] = t0; bh[1][0] = t1; bh[0][1] = t2; bh[1][1] = t3;
                #pragma unroll
                for (int u = 0; u < 2; u++)
                    mma_f16(S[2*jp+u], qf[kq], bh[u]);
            }
        }

        const int kv0 = ck * 64;
        const int row0 = q0 + wid * 16 + g4;
        #pragma unroll
        for (int j = 0; j < 8; j++) {
            const int col = kv0 + j * 8 + t4 * 2;
            float2 bz0 = *(const float2*)(bptr + (size_t)row0 * SQ + col);
            float2 bz1 = *(const float2*)(bptr + (size_t)(row0 + 8) * SQ + col);
            S[j][0] = S[j][0] * 0.125f + bz0.x;
            S[j][1] = S[j][1] * 0.125f + bz0.y;
            S[j][2] = S[j][2] * 0.125f + bz1.x;
            S[j][3] = S[j][3] * 0.125f + bz1.y;
        }

        float m0 = -1e30f, m1 = -1e30f;
        #pragma unroll
        for (int j = 0; j < 8; j++) {
            m0 = fmaxf(m0, fmaxf(S[j][0], S[j][1]));
            m1 = fmaxf(m1, fmaxf(S[j][2], S[j][3]));
        }
        m0 = fmaxf(m0, __shfl_xor_sync(0xffffffffu, m0, 1));
        m0 = fmaxf(m0, __shfl_xor_sync(0xffffffffu, m0, 2));
        m1 = fmaxf(m1, __shfl_xor_sync(0xffffffffu, m1, 1));
        m1 = fmaxf(m1, __shfl_xor_sync(0xffffffffu, m1, 2));
        const float nm0 = fmaxf(rm0, m0), nm1 = fmaxf(rm1, m1);
        const float f0 = __expf(rm0 - nm0), f1 = __expf(rm1 - nm1);
        float ls0 = 0.0f, ls1 = 0.0f;
        #pragma unroll
        for (int j = 0; j < 8; j++) {
            S[j][0] = __expf(S[j][0] - nm0); ls0 += S[j][0];
            S[j][1] = __expf(S[j][1] - nm0); ls0 += S[j][1];
            S[j][2] = __expf(S[j][2] - nm1); ls1 += S[j][2];
            S[j][3] = __expf(S[j][3] - nm1); ls1 += S[j][3];
        }
        rs0 = rs0 * f0 + ls0;
        rs1 = rs1 * f1 + ls1;
        rm0 = nm0; rm1 = nm1;
        #pragma unroll
        for (int d = 0; d < 8; d++) {
            o[d][0] *= f0; o[d][1] *= f0; o[d][2] *= f1; o[d][3] *= f1;
        }

        u32 pa[4][4];
        #pragma unroll
        for (int kp = 0; kp < 4; kp++) {
            pa[kp][0] = pack2f(S[2*kp][0],   S[2*kp][1]);
            pa[kp][1] = pack2f(S[2*kp][2],   S[2*kp][3]);
            pa[kp][2] = pack2f(S[2*kp+1][0], S[2*kp+1][1]);
            pa[kp][3] = pack2f(S[2*kp+1][2], S[2*kp+1][3]);
        }

        const u32 vbase = st + HKV;
        const u32 vrow  = (u32)((lane & 7) + 8 * ((lane >> 3) & 1));
        const u32 vcolb = (u32)((lane >> 4) * 16);
        #pragma unroll
        for (int kp = 0; kp < 4; kp++) {
            #pragma unroll
            for (int dp = 0; dp < 4; dp++) {
                u32 vd = vbase + (u32)((kp * 16 + vrow) * ROWB) + (u32)(dp * 32) + vcolb;
                u32 r0, r1, r2, r3;
                u32 vhf[2][2];
                LDSM4T(r0, r1, r2, r3, vd);
                vhf[0][0] = r0; vhf[0][1] = r1; vhf[1][0] = r2; vhf[1][1] = r3;
                #pragma unroll
                for (int u = 0; u < 2; u++)
                    mma_f16(o[2*dp+u], pa[kp], vhf[u]);
            }
        }
    }

    rs0 += __shfl_xor_sync(0xffffffffu, rs0, 1);
    rs0 += __shfl_xor_sync(0xffffffffu, rs0, 2);
    rs1 += __shfl_xor_sync(0xffffffffu, rs1, 1);
    rs1 += __shfl_xor_sync(0xffffffffu, rs1, 2);
    const float i0 = 1.0f / rs0, i1 = 1.0f / rs1;
    const int row0 = q0 + wid * 16 + g4;
    #pragma unroll
    for (int d = 0; d < 8; d++) {
        const int col = h * 64 + d * 8 + t4 * 2;
        *(u32*)(og + ((size_t)b * SQ + row0) * DM + col)     = pack2f(o[d][0] * i0, o[d][1] * i0);
        *(u32*)(og + ((size_t)b * SQ + row0 + 8) * DM + col) = pack2f(o[d][2] * i1, o[d][3] * i1);
    }
}

// ------------------- merged convert fp32 -> fp16 -------------------
struct SplitTab {
    const float* x[8];
    h16* h[8];
    int endblk[8];
};

__global__ __launch_bounds__(256)
void splitall_k(SplitTab t)
{
    int bk = blockIdx.x;
    int r = 0;
    #pragma unroll
    for (int j = 0; j < 8; j++) if (bk >= t.endblk[j]) r = j + 1;
    int start = r ? t.endblk[r - 1] : 0;
    size_t i = (size_t)(bk - start) * 256 + threadIdx.x;
    float4 v = ((const float4*)t.x[r])[i];
    ((uint2*)t.h[r])[i] = make_uint2(pack2f(v.x, v.y), pack2f(v.z, v.w));
}

// ------------------- LayerNorm rows of 1024 -------------------
template<int OUTM>   // 0: fp32 y; 1: fp16 yh
__global__ __launch_bounds__(256)
void ln_k(const float* __restrict__ x, float* __restrict__ y,
          h16* __restrict__ yh,
          const float* __restrict__ gg, const float* __restrict__ bb)
{
    const float* p = x + (size_t)blockIdx.x * DM;
    const int tid = threadIdx.x, lane = tid & 31, warp = tid >> 5;
    __shared__ float r1[8], r2[8];

    float4 v4 = ((const float4*)p)[tid];
    float v[4] = {v4.x, v4.y, v4.z, v4.w};
    float sm = v[0]+v[1]+v[2]+v[3];
    float s2 = v[0]*v[0]+v[1]*v[1]+v[2]*v[2]+v[3]*v[3];
    #pragma unroll
    for (int o = 16; o; o >>= 1) {
        sm += __shfl_xor_sync(0xffffffffu, sm, o);
        s2 += __shfl_xor_sync(0xffffffffu, s2, o);
    }
    if (!lane) { r1[warp] = sm; r2[warp] = s2; }
    __syncthreads();
    sm = 0.0f; s2 = 0.0f;
    #pragma unroll
    for (int i = 0; i < 8; i++) { sm += r1[i]; s2 += r2[i]; }
    const float mean = sm * (1.0f / DM);
    const float var  = s2 * (1.0f / DM) - mean * mean;
    const float inv  = rsqrtf(var + 1e-5f);

    float4 g4 = ((const float4*)gg)[tid];
    float4 b4 = ((const float4*)bb)[tid];
    float o0 = (v[0]-mean)*inv*g4.x + b4.x;
    float o1 = (v[1]-mean)*inv*g4.y + b4.y;
    float o2 = (v[2]-mean)*inv*g4.z + b4.z;
    float o3 = (v[3]-mean)*inv*g4.w + b4.w;
    if (OUTM == 0) {
        ((float4*)(y + (size_t)blockIdx.x * DM))[tid] = make_float4(o0,o1,o2,o3);
    } else {
        ((uint2*)(yh + (size_t)blockIdx.x * DM))[tid] = make_uint2(pack2f(o0,o1), pack2f(o2,o3));
    }
}

// ------------------- launch -------------------
#define SMEM_GEMM (3 * 2 * 128 * 80)    // 61440
#define SMEM_FLASH (2 * 2 * 64 * 144)   // 36864

extern "C" void kernel_launch(void* const* d_in, const int* in_sizes, int n_in,
                              void* d_out, int out_size)
{
    const float* x_q  = (const float*)d_in[0];
    const float* x_kv = (const float*)d_in[1];
    const float* bias = (const float*)d_in[2];
    const float* Wq   = (const float*)d_in[3];
    const float* Wk   = (const float*)d_in[4];
    const float* Wv   = (const float*)d_in[5];
    const float* Wo   = (const float*)d_in[6];
    const float* W1   = (const float*)d_in[7];
    const float* b1   = (const float*)d_in[8];
    const float* W2   = (const float*)d_in[9];
    const float* b2   = (const float*)d_in[10];
    const float* g1   = (const float*)d_in[11];
    const float* be1  = (const float*)d_in[12];
    const float* g2   = (const float*)d_in[13];
    const float* be2  = (const float*)d_in[14];
    float* out = (float*)d_out;

    h16 *xq,*xk,*wq,*wk,*wv,*wo,*w1,*w2;
    h16 *q,*k,*v,*o,*ln,*hh;
    float *x1,*x2;
    cudaGetSymbolAddress((void**)&xq, s_xq);
    cudaGetSymbolAddress((void**)&xk, s_xk);
    cudaGetSymbolAddress((void**)&wq, s_wq);
    cudaGetSymbolAddress((void**)&wk, s_wk);
    cudaGetSymbolAddress((void**)&wv, s_wv);
    cudaGetSymbolAddress((void**)&wo, s_wo);
    cudaGetSymbolAddress((void**)&w1, s_w1);
    cudaGetSymbolAddress((void**)&w2, s_w2);
    cudaGetSymbolAddress((void**)&q,  s_q);
    cudaGetSymbolAddress((void**)&k,  s_k);
    cudaGetSymbolAddress((void**)&v,  s_v);
    cudaGetSymbolAddress((void**)&o,  s_o);
    cudaGetSymbolAddress((void**)&x1, s_x1);
    cudaGetSymbolAddress((void**)&ln, s_ln);
    cudaGetSymbolAddress((void**)&hh, s_h);
    cudaGetSymbolAddress((void**)&x2, s_x2);

    cudaFuncSetAttribute(gemm_mma<1,0>, cudaFuncAttributeMaxDynamicSharedMemorySize, SMEM_GEMM);
    cudaFuncSetAttribute(gemm_mma<2,1>, cudaFuncAttributeMaxDynamicSharedMemorySize, SMEM_GEMM);
    cudaFuncSetAttribute(gemm_mma<3,0>, cudaFuncAttributeMaxDynamicSharedMemorySize, SMEM_GEMM);
    cudaFuncSetAttribute(gemm_qkv,      cudaFuncAttributeMaxDynamicSharedMemorySize, SMEM_GEMM);
    cudaFuncSetAttribute(flash_k,       cudaFuncAttributeMaxDynamicSharedMemorySize, SMEM_FLASH);

    // one merged conversion launch: everything to single fp16
    {
        SplitTab t;
        t.x[0]=x_q;  t.h[0]=xq;
        t.x[1]=x_kv; t.h[1]=xk;
        t.x[2]=Wq;   t.h[2]=wq;
        t.x[3]=Wk;   t.h[3]=wk;
        t.x[4]=Wv;   t.h[4]=wv;
        t.x[5]=Wo;   t.h[5]=wo;
        t.x[6]=W1;   t.h[6]=w1;
        t.x[7]=W2;   t.h[7]=w2;
        int blks[8] = {MR*DM/1024, MR*DM/1024, DM*DM/1024, DM*DM/1024,
                       DM*DM/1024, DM*DM/1024, FF*DM/1024, DM*FF/1024};
        int acc_ = 0;
        for (int j = 0; j < 8; j++) { acc_ += blks[j]; t.endblk[j] = acc_; }
        splitall_k<<<acc_, 256>>>(t);
    }

    // Q, K, V projections in ONE batched launch
    {
        QKVArgs a;
        a.Ah[0]=xq; a.Bh[0]=wq; a.Ch[0]=q;
        a.Ah[1]=xk; a.Bh[1]=wk; a.Ch[1]=k;
        a.Ah[2]=xk; a.Bh[2]=wv; a.Ch[2]=v;
        gemm_qkv<<<dim3(DM/128, MR/128, 3), 128, SMEM_GEMM>>>(a);
    }

    // fused attention
    flash_k<<<dim3(SQ/128, NHD, BB), 256, SMEM_FLASH>>>(q, k, v, bias, o);

    // x1 = x_q + O @ Wo^T
    gemm_mma<1,0><<<dim3(DM/128, MR/128, 1), 128, SMEM_GEMM>>>(
        o, wo, x1, nullptr,
        DM, DM, DM, DM, 1.0f, x_q, DM, nullptr);

    ln_k<1><<<MR, 256>>>(x1, nullptr, ln, g1, be1);

    // h = gelu(ln1 @ W1^T + b1)
    gemm_mma<2,1><<<dim3(FF/128, MR/128, 1), 128, SMEM_GEMM>>>(
        ln, w1, nullptr, hh,
        DM, DM, DM, FF, 1.0f, nullptr, 0, b1);

    // x2 = x1 + h @ W2^T + b2
    gemm_mma<3,0><<<dim3(DM/128, MR/128, 1), 128, SMEM_GEMM>>>(
        hh, w2, x2, nullptr,
        FF, FF, FF, DM, 1.0f, x1, DM, b2);

    ln_k<0><<<MR, 256>>>(x2, out, nullptr, g2, be2);
}

// round 15
// speedup vs baseline: 1.1465x; 1.1465x over previous
#include <cuda_runtime.h>
#include <cuda_fp16.h>
#include <cstdint>
#include <math.h>

typedef __half h16;
typedef unsigned int u32;

#define BB 2
#define SQ 2048
#define DM 1024
#define NHD 16
#define FF 4096
#define MR (BB*SQ)

// ------------------- scratch (device globals) -------------------
__device__ h16 s_xq[MR*DM];
__device__ h16 s_xk[MR*DM];
__device__ h16 s_wq[DM*DM];
__device__ h16 s_wk[DM*DM];
__device__ h16 s_wv[DM*DM];
__device__ h16 s_wo[DM*DM];
__device__ h16 s_w1[FF*DM];
__device__ h16 s_w2[DM*FF];
__device__ h16 s_q[MR*DM];
__device__ h16 s_k[MR*DM];
__device__ h16 s_v[MR*DM];
__device__ h16 s_o[MR*DM];
__device__ float s_x1[MR*DM];
__device__ h16 s_ln[MR*DM];
__device__ h16 s_h[(size_t)MR*FF];
__device__ float s_x2[MR*DM];

// ------------------- helpers -------------------
__device__ __forceinline__ u32 smem_u32(const void* p) {
    return (u32)__cvta_generic_to_shared(p);
}
#define CP16(dst, src) \
    asm volatile("cp.async.cg.shared.global [%0], [%1], 16;" :: "r"(dst), "l"(src))
#define CP_COMMIT() asm volatile("cp.async.commit_group;" ::: "memory")
#define CP_WAIT0()  asm volatile("cp.async.wait_group 0;" ::: "memory")

#define LDSM4(r0, r1, r2, r3, addr) \
    asm volatile("ldmatrix.sync.aligned.m8n8.x4.shared.b16 {%0,%1,%2,%3}, [%4];" \
        : "=r"(r0), "=r"(r1), "=r"(r2), "=r"(r3) : "r"(addr))
#define LDSM4T(r0, r1, r2, r3, addr) \
    asm volatile("ldmatrix.sync.aligned.m8n8.x4.trans.shared.b16 {%0,%1,%2,%3}, [%4];" \
        : "=r"(r0), "=r"(r1), "=r"(r2), "=r"(r3) : "r"(addr))

__device__ __forceinline__ void mma_f16(float* c, const u32* a, const u32* b) {
    asm volatile("mma.sync.aligned.m16n8k16.row.col.f32.f16.f16.f32 "
        "{%0,%1,%2,%3}, {%4,%5,%6,%7}, {%8,%9}, {%0,%1,%2,%3};"
        : "+f"(c[0]), "+f"(c[1]), "+f"(c[2]), "+f"(c[3])
        : "r"(a[0]), "r"(a[1]), "r"(a[2]), "r"(a[3]), "r"(b[0]), "r"(b[1]));
}

__device__ __forceinline__ u32 pack2(h16 a, h16 b) {
    return (u32)__half_as_ushort(a) | ((u32)__half_as_ushort(b) << 16);
}
__device__ __forceinline__ u32 pack2f(float a, float b) {
    return pack2(__float2half_rn(a), __float2half_rn(b));
}

// ===================================================================
// GEMM config: BM=BN=128, BK=32, 256 thr, 2Mx4N warps, warp tile 64x32.
// A, B single fp16. 2-stage cp.async, 40KB smem -> 2 CTAs/SM (16 warps).
// ===================================================================
#define G_ROWB  80u
#define G_B_OFF (128u * G_ROWB)
#define G_STG   (2u * 128u * G_ROWB)   // 20480 per stage

// ------------------- HMMA GEMM (generic) -------------------
// C[m,n] = alpha * sum_k A[m,k]*B[n,k] (+ epilogue)
// EPI: 0 none; 1 +addM; 2 +biasN then GELU; 3 +addM +biasN
// OUTM: 0 -> fp32 C; 1 -> fp16 Ch
template<int EPI, int OUTM>
__global__ __launch_bounds__(256, 2)
void gemm_mma(const h16* __restrict__ Ah, const h16* __restrict__ Bh,
              float* __restrict__ C, h16* __restrict__ Ch,
              int K, int lda, int ldb, int ldc,
              float alpha,
              const float* __restrict__ addM, int ldadd,
              const float* __restrict__ biasN)
{
    extern __shared__ char smem[];
    const u32 sbase = smem_u32(smem);
    const int tid = threadIdx.x, lane = tid & 31, wid = tid >> 5;
    const int wm = wid & 1, wn = wid >> 1;     // 2 x 4

    const int m0 = blockIdx.y * 128, n0 = blockIdx.x * 128;

    float acc[4][4][4];
    #pragma unroll
    for (int i = 0; i < 4; i++)
        #pragma unroll
        for (int j = 0; j < 4; j++)
            #pragma unroll
            for (int t = 0; t < 4; t++) acc[i][j][t] = 0.0f;

    auto load_chunk = [&](int ck, int st) {
        const int k0 = ck * 32;
        const u32 sa = sbase + (u32)st * G_STG;
        #pragma unroll
        for (int it = 0; it < 2; it++) {
            int a = tid + it * 256;            // 0..511
            int row = a >> 2, ch = a & 3;
            u32 dst = sa + (u32)row * G_ROWB + (u32)ch * 16;
            CP16(dst,           Ah + (size_t)(m0 + row) * lda + k0 + ch * 8);
            CP16(dst + G_B_OFF, Bh + (size_t)(n0 + row) * ldb + k0 + ch * 8);
        }
    };

    auto compute = [&](int st) {
        const u32 ab  = sbase + (u32)st * G_STG;
        const u32 bb  = ab + G_B_OFF;
        const u32 rb  = (u32)((lane & 15) * G_ROWB);
        #pragma unroll
        for (int s16 = 0; s16 < 2; s16++) {
            const u32 coff = (u32)(s16 * 32 + (lane >> 4) * 16);
            u32 bh[4][2];
            #pragma unroll
            for (int np = 0; np < 2; np++) {
                u32 bd = bb + (u32)((wn * 32 + np * 16) * G_ROWB) + rb + coff;
                u32 t0, t1, t2, t3;
                LDSM4(t0, t1, t2, t3, bd);
                bh[2*np][0] = t0; bh[2*np+1][0] = t1; bh[2*np][1] = t2; bh[2*np+1][1] = t3;
            }
            #pragma unroll
            for (int mt = 0; mt < 4; mt++) {
                u32 ah[4];
                u32 ad = ab + (u32)((wm * 64 + mt * 16) * G_ROWB) + rb + coff;
                LDSM4(ah[0], ah[1], ah[2], ah[3], ad);
                #pragma unroll
                for (int nt = 0; nt < 4; nt++)
                    mma_f16(acc[mt][nt], ah, bh[nt]);
            }
        }
    };

    const int NC = K >> 5;
    load_chunk(0, 0); CP_COMMIT();
    for (int i = 0; i < NC; i++) {
        CP_WAIT0();
        __syncthreads();
        if (i + 1 < NC) { load_chunk(i + 1, (i + 1) & 1); CP_COMMIT(); }
        compute(i & 1);
    }

    auto proc2 = [&](int gm, int gn, float v0, float v1) {
        v0 *= alpha; v1 *= alpha;
        if (EPI == 1 || EPI == 3) {
            float2 ad = *(const float2*)(addM + (size_t)gm * ldadd + gn);
            v0 += ad.x; v1 += ad.y;
        }
        if (EPI == 2 || EPI == 3) {
            float2 bn2 = *(const float2*)(biasN + gn);
            v0 += bn2.x; v1 += bn2.y;
        }
        if (EPI == 2) {
            v0 = 0.5f * v0 * (1.0f + erff(v0 * 0.70710678118654752f));
            v1 = 0.5f * v1 * (1.0f + erff(v1 * 0.70710678118654752f));
        }
        if (OUTM == 0) {
            *(float2*)(C + (size_t)gm * ldc + gn) = make_float2(v0, v1);
        } else {
            *(u32*)(Ch + (size_t)gm * ldc + gn) = pack2f(v0, v1);
        }
    };

    const int r  = lane >> 2;
    const int c2 = (lane & 3) * 2;
    #pragma unroll
    for (int mt = 0; mt < 4; mt++) {
        #pragma unroll
        for (int nt = 0; nt < 4; nt++) {
            int gm = m0 + wm * 64 + mt * 16 + r;
            int gn = n0 + wn * 32 + nt * 8 + c2;
            proc2(gm,     gn, acc[mt][nt][0], acc[mt][nt][1]);
            proc2(gm + 8, gn, acc[mt][nt][2], acc[mt][nt][3]);
        }
    }
}

// ------------------- batched QKV GEMM (z selects matrix triple) -------------------
struct QKVArgs {
    const h16* Ah[3];
    const h16* Bh[3];
    h16* Ch[3];
};

__global__ __launch_bounds__(256, 2)
void gemm_qkv(QKVArgs args)
{
    extern __shared__ char smem[];
    const u32 sbase = smem_u32(smem);
    const int tid = threadIdx.x, lane = tid & 31, wid = tid >> 5;
    const int wm = wid & 1, wn = wid >> 1;
    const int zz = blockIdx.z;

    const h16* __restrict__ Ah = args.Ah[zz];
    const h16* __restrict__ Bh = args.Bh[zz];
    h16* __restrict__ Ch = args.Ch[zz];

    const int m0 = blockIdx.y * 128, n0 = blockIdx.x * 128;

    float acc[4][4][4];
    #pragma unroll
    for (int i = 0; i < 4; i++)
        #pragma unroll
        for (int j = 0; j < 4; j++)
            #pragma unroll
            for (int t = 0; t < 4; t++) acc[i][j][t] = 0.0f;

    auto load_chunk = [&](int ck, int st) {
        const int k0 = ck * 32;
        const u32 sa = sbase + (u32)st * G_STG;
        #pragma unroll
        for (int it = 0; it < 2; it++) {
            int a = tid + it * 256;
            int row = a >> 2, ch = a & 3;
            u32 dst = sa + (u32)row * G_ROWB + (u32)ch * 16;
            CP16(dst,           Ah + (size_t)(m0 + row) * DM + k0 + ch * 8);
            CP16(dst + G_B_OFF, Bh + (size_t)(n0 + row) * DM + k0 + ch * 8);
        }
    };

    auto compute = [&](int st) {
        const u32 ab  = sbase + (u32)st * G_STG;
        const u32 bb  = ab + G_B_OFF;
        const u32 rb  = (u32)((lane & 15) * G_ROWB);
        #pragma unroll
        for (int s16 = 0; s16 < 2; s16++) {
            const u32 coff = (u32)(s16 * 32 + (lane >> 4) * 16);
            u32 bh[4][2];
            #pragma unroll
            for (int np = 0; np < 2; np++) {
                u32 bd = bb + (u32)((wn * 32 + np * 16) * G_ROWB) + rb + coff;
                u32 t0, t1, t2, t3;
                LDSM4(t0, t1, t2, t3, bd);
                bh[2*np][0] = t0; bh[2*np+1][0] = t1; bh[2*np][1] = t2; bh[2*np+1][1] = t3;
            }
            #pragma unroll
            for (int mt = 0; mt < 4; mt++) {
                u32 ah[4];
                u32 ad = ab + (u32)((wm * 64 + mt * 16) * G_ROWB) + rb + coff;
                LDSM4(ah[0], ah[1], ah[2], ah[3], ad);
                #pragma unroll
                for (int nt = 0; nt < 4; nt++)
                    mma_f16(acc[mt][nt], ah, bh[nt]);
            }
        }
    };

    const int NC = DM >> 5;
    load_chunk(0, 0); CP_COMMIT();
    for (int i = 0; i < NC; i++) {
        CP_WAIT0();
        __syncthreads();
        if (i + 1 < NC) { load_chunk(i + 1, (i + 1) & 1); CP_COMMIT(); }
        compute(i & 1);
    }

    const int r  = lane >> 2;
    const int c2 = (lane & 3) * 2;
    #pragma unroll
    for (int mt = 0; mt < 4; mt++) {
        #pragma unroll
        for (int nt = 0; nt < 4; nt++) {
            int gm = m0 + wm * 64 + mt * 16 + r;
            int gn = n0 + wn * 32 + nt * 8 + c2;
            *(u32*)(Ch + (size_t)gm * DM + gn)       = pack2f(acc[mt][nt][0], acc[mt][nt][1]);
            *(u32*)(Ch + (size_t)(gm + 8) * DM + gn) = pack2f(acc[mt][nt][2], acc[mt][nt][3]);
        }
    }
}

// ------------------- fused flash attention (all single fp16) -------------------
__global__ __launch_bounds__(256, 2)
void flash_k(const h16* __restrict__ qg,
             const h16* __restrict__ kh, const h16* __restrict__ vh,
             const float* __restrict__ bias,
             h16* __restrict__ og)
{
    constexpr u32 ROWB = 144;
    constexpr u32 HKV  = 64 * ROWB;
    constexpr u32 STG  = 2 * HKV;

    extern __shared__ char smem[];
    const u32 sbase = smem_u32(smem);
    const int tid = threadIdx.x, lane = tid & 31, wid = tid >> 5;
    const int b = blockIdx.z, h = blockIdx.y, q0 = blockIdx.x * 128;

    const size_t qbase = ((size_t)b * SQ + q0) * DM + h * 64;
    const size_t kvbase = (size_t)b * SQ * DM + h * 64;
    const float* bptr = bias + ((size_t)(b * NHD + h)) * SQ * SQ;

    #pragma unroll
    for (int it = 0; it < 4; it++) {
        int idx = tid + it * 256;
        int row = idx >> 3, c8 = idx & 7;
        u32 dst = sbase + (u32)row * ROWB + (u32)c8 * 16;
        CP16(dst, qg + qbase + (size_t)row * DM + c8 * 8);
    }
    CP_COMMIT(); CP_WAIT0();
    __syncthreads();

    u32 qf[4][4];
    {
        const u32 base = sbase + (u32)((wid * 16 + (lane & 15)) * ROWB);
        #pragma unroll
        for (int kq = 0; kq < 4; kq++) {
            u32 ad = base + (u32)(kq * 32 + (lane >> 4) * 16);
            LDSM4(qf[kq][0], qf[kq][1], qf[kq][2], qf[kq][3], ad);
        }
    }
    __syncthreads();

    auto load_kv = [&](int ck, u32 st) {
        const int kv0 = ck * 64;
        #pragma unroll
        for (int it = 0; it < 2; it++) {
            int idx = tid + it * 256;
            int row = idx >> 3, c8 = idx & 7;
            size_t g = kvbase + (size_t)(kv0 + row) * DM + c8 * 8;
            u32 dst = st + (u32)row * ROWB + (u32)c8 * 16;
            CP16(dst,       kh + g);
            CP16(dst + HKV, vh + g);
        }
    };

    float o[8][4];
    #pragma unroll
    for (int d = 0; d < 8; d++)
        #pragma unroll
        for (int t = 0; t < 4; t++) o[d][t] = 0.0f;
    float rm0 = -1e30f, rm1 = -1e30f, rs0 = 0.0f, rs1 = 0.0f;

    load_kv(0, sbase); CP_COMMIT();

    const u32 rbA = (u32)((lane & 15) * ROWB);
    const int g4  = lane >> 2, t4 = lane & 3;

    for (int ck = 0; ck < SQ / 64; ck++) {
        const u32 st = sbase + (u32)(ck & 1) * STG;
        CP_WAIT0();
        __syncthreads();
        if (ck + 1 < SQ / 64) { load_kv(ck + 1, sbase + (u32)((ck + 1) & 1) * STG); CP_COMMIT(); }

        float S[8][4];
        #pragma unroll
        for (int j = 0; j < 8; j++)
            #pragma unroll
            for (int t = 0; t < 4; t++) S[j][t] = 0.0f;

        #pragma unroll
        for (int kq = 0; kq < 4; kq++) {
            const u32 coff = (u32)(kq * 32 + (lane >> 4) * 16);
            #pragma unroll
            for (int jp = 0; jp < 4; jp++) {
                u32 kd = st + (u32)(jp * 16 * ROWB) + rbA + coff;
                u32 t0, t1, t2, t3;
                u32 bh[2][2];
                LDSM4(t0, t1, t2, t3, kd);
                bh[0][0] = t0; bh[1][0] = t1; bh[0][1] = t2; bh[1][1] = t3;
                #pragma unroll
                for (int u = 0; u < 2; u++)
                    mma_f16(S[2*jp+u], qf[kq], bh[u]);
            }
        }

        const int kv0 = ck * 64;
        const int row0 = q0 + wid * 16 + g4;
        #pragma unroll
        for (int j = 0; j < 8; j++) {
            const int col = kv0 + j * 8 + t4 * 2;
            float2 bz0 = *(const float2*)(bptr + (size_t)row0 * SQ + col);
            float2 bz1 = *(const float2*)(bptr + (size_t)(row0 + 8) * SQ + col);
            S[j][0] = S[j][0] * 0.125f + bz0.x;
            S[j][1] = S[j][1] * 0.125f + bz0.y;
            S[j][2] = S[j][2] * 0.125f + bz1.x;
            S[j][3] = S[j][3] * 0.125f + bz1.y;
        }

        float m0 = -1e30f, m1 = -1e30f;
        #pragma unroll
        for (int j = 0; j < 8; j++) {
            m0 = fmaxf(m0, fmaxf(S[j][0], S[j][1]));
            m1 = fmaxf(m1, fmaxf(S[j][2], S[j][3]));
        }
        m0 = fmaxf(m0, __shfl_xor_sync(0xffffffffu, m0, 1));
        m0 = fmaxf(m0, __shfl_xor_sync(0xffffffffu, m0, 2));
        m1 = fmaxf(m1, __shfl_xor_sync(0xffffffffu, m1, 1));
        m1 = fmaxf(m1, __shfl_xor_sync(0xffffffffu, m1, 2));
        const float nm0 = fmaxf(rm0, m0), nm1 = fmaxf(rm1, m1);
        const float f0 = __expf(rm0 - nm0), f1 = __expf(rm1 - nm1);
        float ls0 = 0.0f, ls1 = 0.0f;
        #pragma unroll
        for (int j = 0; j < 8; j++) {
            S[j][0] = __expf(S[j][0] - nm0); ls0 += S[j][0];
            S[j][1] = __expf(S[j][1] - nm0); ls0 += S[j][1];
            S[j][2] = __expf(S[j][2] - nm1); ls1 += S[j][2];
            S[j][3] = __expf(S[j][3] - nm1); ls1 += S[j][3];
        }
        rs0 = rs0 * f0 + ls0;
        rs1 = rs1 * f1 + ls1;
        rm0 = nm0; rm1 = nm1;
        #pragma unroll
        for (int d = 0; d < 8; d++) {
            o[d][0] *= f0; o[d][1] *= f0; o[d][2] *= f1; o[d][3] *= f1;
        }

        u32 pa[4][4];
        #pragma unroll
        for (int kp = 0; kp < 4; kp++) {
            pa[kp][0] = pack2f(S[2*kp][0],   S[2*kp][1]);
            pa[kp][1] = pack2f(S[2*kp][2],   S[2*kp][3]);
            pa[kp][2] = pack2f(S[2*kp+1][0], S[2*kp+1][1]);
            pa[kp][3] = pack2f(S[2*kp+1][2], S[2*kp+1][3]);
        }

        const u32 vbase = st + HKV;
        const u32 vrow  = (u32)((lane & 7) + 8 * ((lane >> 3) & 1));
        const u32 vcolb = (u32)((lane >> 4) * 16);
        #pragma unroll
        for (int kp = 0; kp < 4; kp++) {
            #pragma unroll
            for (int dp = 0; dp < 4; dp++) {
                u32 vd = vbase + (u32)((kp * 16 + vrow) * ROWB) + (u32)(dp * 32) + vcolb;
                u32 r0, r1, r2, r3;
                u32 vhf[2][2];
                LDSM4T(r0, r1, r2, r3, vd);
                vhf[0][0] = r0; vhf[0][1] = r1; vhf[1][0] = r2; vhf[1][1] = r3;
                #pragma unroll
                for (int u = 0; u < 2; u++)
                    mma_f16(o[2*dp+u], pa[kp], vhf[u]);
            }
        }
    }

    rs0 += __shfl_xor_sync(0xffffffffu, rs0, 1);
    rs0 += __shfl_xor_sync(0xffffffffu, rs0, 2);
    rs1 += __shfl_xor_sync(0xffffffffu, rs1, 1);
    rs1 += __shfl_xor_sync(0xffffffffu, rs1, 2);
    const float i0 = 1.0f / rs0, i1 = 1.0f / rs1;
    const int row0 = q0 + wid * 16 + g4;
    #pragma unroll
    for (int d = 0; d < 8; d++) {
        const int col = h * 64 + d * 8 + t4 * 2;
        *(u32*)(og + ((size_t)b * SQ + row0) * DM + col)     = pack2f(o[d][0] * i0, o[d][1] * i0);
        *(u32*)(og + ((size_t)b * SQ + row0 + 8) * DM + col) = pack2f(o[d][2] * i1, o[d][3] * i1);
    }
}

// ------------------- merged convert fp32 -> fp16 -------------------
struct SplitTab {
    const float* x[8];
    h16* h[8];
    int endblk[8];
};

__global__ __launch_bounds__(256)
void splitall_k(SplitTab t)
{
    int bk = blockIdx.x;
    int r = 0;
    #pragma unroll
    for (int j = 0; j < 8; j++) if (bk >= t.endblk[j]) r = j + 1;
    int start = r ? t.endblk[r - 1] : 0;
    size_t i = (size_t)(bk - start) * 256 + threadIdx.x;
    float4 v = ((const float4*)t.x[r])[i];
    ((uint2*)t.h[r])[i] = make_uint2(pack2f(v.x, v.y), pack2f(v.z, v.w));
}

// ------------------- LayerNorm rows of 1024 -------------------
template<int OUTM>   // 0: fp32 y; 1: fp16 yh
__global__ __launch_bounds__(256)
void ln_k(const float* __restrict__ x, float* __restrict__ y,
          h16* __restrict__ yh,
          const float* __restrict__ gg, const float* __restrict__ bb)
{
    const float* p = x + (size_t)blockIdx.x * DM;
    const int tid = threadIdx.x, lane = tid & 31, warp = tid >> 5;
    __shared__ float r1[8], r2[8];

    float4 v4 = ((const float4*)p)[tid];
    float v[4] = {v4.x, v4.y, v4.z, v4.w};
    float sm = v[0]+v[1]+v[2]+v[3];
    float s2 = v[0]*v[0]+v[1]*v[1]+v[2]*v[2]+v[3]*v[3];
    #pragma unroll
    for (int o = 16; o; o >>= 1) {
        sm += __shfl_xor_sync(0xffffffffu, sm, o);
        s2 += __shfl_xor_sync(0xffffffffu, s2, o);
    }
    if (!lane) { r1[warp] = sm; r2[warp] = s2; }
    __syncthreads();
    sm = 0.0f; s2 = 0.0f;
    #pragma unroll
    for (int i = 0; i < 8; i++) { sm += r1[i]; s2 += r2[i]; }
    const float mean = sm * (1.0f / DM);
    const float var  = s2 * (1.0f / DM) - mean * mean;
    const float inv  = rsqrtf(var + 1e-5f);

    float4 g4 = ((const float4*)gg)[tid];
    float4 b4 = ((const float4*)bb)[tid];
    float o0 = (v[0]-mean)*inv*g4.x + b4.x;
    float o1 = (v[1]-mean)*inv*g4.y + b4.y;
    float o2 = (v[2]-mean)*inv*g4.z + b4.z;
    float o3 = (v[3]-mean)*inv*g4.w + b4.w;
    if (OUTM == 0) {
        ((float4*)(y + (size_t)blockIdx.x * DM))[tid] = make_float4(o0,o1,o2,o3);
    } else {
        ((uint2*)(yh + (size_t)blockIdx.x * DM))[tid] = make_uint2(pack2f(o0,o1), pack2f(o2,o3));
    }
}

// ------------------- launch -------------------
#define SMEM_GEMM (2 * 2 * 128 * 80)    // 40960
#define SMEM_FLASH (2 * 2 * 64 * 144)   // 36864

extern "C" void kernel_launch(void* const* d_in, const int* in_sizes, int n_in,
                              void* d_out, int out_size)
{
    const float* x_q  = (const float*)d_in[0];
    const float* x_kv = (const float*)d_in[1];
    const float* bias = (const float*)d_in[2];
    const float* Wq   = (const float*)d_in[3];
    const float* Wk   = (const float*)d_in[4];
    const float* Wv   = (const float*)d_in[5];
    const float* Wo   = (const float*)d_in[6];
    const float* W1   = (const float*)d_in[7];
    const float* b1   = (const float*)d_in[8];
    const float* W2   = (const float*)d_in[9];
    const float* b2   = (const float*)d_in[10];
    const float* g1   = (const float*)d_in[11];
    const float* be1  = (const float*)d_in[12];
    const float* g2   = (const float*)d_in[13];
    const float* be2  = (const float*)d_in[14];
    float* out = (float*)d_out;

    h16 *xq,*xk,*wq,*wk,*wv,*wo,*w1,*w2;
    h16 *q,*k,*v,*o,*ln,*hh;
    float *x1,*x2;
    cudaGetSymbolAddress((void**)&xq, s_xq);
    cudaGetSymbolAddress((void**)&xk, s_xk);
    cudaGetSymbolAddress((void**)&wq, s_wq);
    cudaGetSymbolAddress((void**)&wk, s_wk);
    cudaGetSymbolAddress((void**)&wv, s_wv);
    cudaGetSymbolAddress((void**)&wo, s_wo);
    cudaGetSymbolAddress((void**)&w1, s_w1);
    cudaGetSymbolAddress((void**)&w2, s_w2);
    cudaGetSymbolAddress((void**)&q,  s_q);
    cudaGetSymbolAddress((void**)&k,  s_k);
    cudaGetSymbolAddress((void**)&v,  s_v);
    cudaGetSymbolAddress((void**)&o,  s_o);
    cudaGetSymbolAddress((void**)&x1, s_x1);
    cudaGetSymbolAddress((void**)&ln, s_ln);
    cudaGetSymbolAddress((void**)&hh, s_h);
    cudaGetSymbolAddress((void**)&x2, s_x2);

    cudaFuncSetAttribute(gemm_mma<1,0>, cudaFuncAttributeMaxDynamicSharedMemorySize, SMEM_GEMM);
    cudaFuncSetAttribute(gemm_mma<2,1>, cudaFuncAttributeMaxDynamicSharedMemorySize, SMEM_GEMM);
    cudaFuncSetAttribute(gemm_mma<3,0>, cudaFuncAttributeMaxDynamicSharedMemorySize, SMEM_GEMM);
    cudaFuncSetAttribute(gemm_qkv,      cudaFuncAttributeMaxDynamicSharedMemorySize, SMEM_GEMM);
    cudaFuncSetAttribute(flash_k,       cudaFuncAttributeMaxDynamicSharedMemorySize, SMEM_FLASH);

    // one merged conversion launch: everything to single fp16
    {
        SplitTab t;
        t.x[0]=x_q;  t.h[0]=xq;
        t.x[1]=x_kv; t.h[1]=xk;
        t.x[2]=Wq;   t.h[2]=wq;
        t.x[3]=Wk;   t.h[3]=wk;
        t.x[4]=Wv;   t.h[4]=wv;
        t.x[5]=Wo;   t.h[5]=wo;
        t.x[6]=W1;   t.h[6]=w1;
        t.x[7]=W2;   t.h[7]=w2;
        int blks[8] = {MR*DM/1024, MR*DM/1024, DM*DM/1024, DM*DM/1024,
                       DM*DM/1024, DM*DM/1024, FF*DM/1024, DM*FF/1024};
        int acc_ = 0;
        for (int j = 0; j < 8; j++) { acc_ += blks[j]; t.endblk[j] = acc_; }
        splitall_k<<<acc_, 256>>>(t);
    }

    // Q, K, V projections in ONE batched launch
    {
        QKVArgs a;
        a.Ah[0]=xq; a.Bh[0]=wq; a.Ch[0]=q;
        a.Ah[1]=xk; a.Bh[1]=wk; a.Ch[1]=k;
        a.Ah[2]=xk; a.Bh[2]=wv; a.Ch[2]=v;
        gemm_qkv<<<dim3(DM/128, MR/128, 3), 256, SMEM_GEMM>>>(a);
    }

    // fused attention
    flash_k<<<dim3(SQ/128, NHD, BB), 256, SMEM_FLASH>>>(q, k, v, bias, o);

    // x1 = x_q + O @ Wo^T
    gemm_mma<1,0><<<dim3(DM/128, MR/128, 1), 256, SMEM_GEMM>>>(
        o, wo, x1, nullptr,
        DM, DM, DM, DM, 1.0f, x_q, DM, nullptr);

    ln_k<1><<<MR, 256>>>(x1, nullptr, ln, g1, be1);

    // h = gelu(ln1 @ W1^T + b1)
    gemm_mma<2,1><<<dim3(FF/128, MR/128, 1), 256, SMEM_GEMM>>>(
        ln, w1, nullptr, hh,
        DM, DM, DM, FF, 1.0f, nullptr, 0, b1);

    // x2 = x1 + h @ W2^T + b2
    gemm_mma<3,0><<<dim3(DM/128, MR/128, 1), 256, SMEM_GEMM>>>(
        hh, w2, x2, nullptr,
        FF, FF, FF, DM, 1.0f, x1, DM, b2);

    ln_k<0><<<MR, 256>>>(x2, out, nullptr, g2, be2);
}

// round 16
// speedup vs baseline: 1.1567x; 1.0089x over previous
#include <cuda_runtime.h>
#include <cuda_fp16.h>
#include <cstdint>
#include <math.h>

typedef __half h16;
typedef unsigned int u32;

#define BB 2
#define SQ 2048
#define DM 1024
#define NHD 16
#define FF 4096
#define MR (BB*SQ)

// ------------------- scratch (device globals) -------------------
__device__ h16 s_xq[MR*DM];
__device__ h16 s_xk[MR*DM];
__device__ h16 s_wq[DM*DM];
__device__ h16 s_wk[DM*DM];
__device__ h16 s_wv[DM*DM];
__device__ h16 s_wo[DM*DM];
__device__ h16 s_w1[FF*DM];
__device__ h16 s_w2[DM*FF];
__device__ h16 s_q[MR*DM];
__device__ h16 s_k[MR*DM];
__device__ h16 s_v[MR*DM];
__device__ h16 s_o[MR*DM];
__device__ float s_x1[MR*DM];
__device__ h16 s_ln[MR*DM];
__device__ h16 s_h[(size_t)MR*FF];
__device__ float s_part[(size_t)2*MR*DM];   // split-K partials

// ------------------- helpers -------------------
__device__ __forceinline__ u32 smem_u32(const void* p) {
    return (u32)__cvta_generic_to_shared(p);
}
#define CP16(dst, src) \
    asm volatile("cp.async.cg.shared.global [%0], [%1], 16;" :: "r"(dst), "l"(src))
#define CP_COMMIT() asm volatile("cp.async.commit_group;" ::: "memory")
#define CP_WAIT0()  asm volatile("cp.async.wait_group 0;" ::: "memory")

#define LDSM4(r0, r1, r2, r3, addr) \
    asm volatile("ldmatrix.sync.aligned.m8n8.x4.shared.b16 {%0,%1,%2,%3}, [%4];" \
        : "=r"(r0), "=r"(r1), "=r"(r2), "=r"(r3) : "r"(addr))
#define LDSM4T(r0, r1, r2, r3, addr) \
    asm volatile("ldmatrix.sync.aligned.m8n8.x4.trans.shared.b16 {%0,%1,%2,%3}, [%4];" \
        : "=r"(r0), "=r"(r1), "=r"(r2), "=r"(r3) : "r"(addr))

__device__ __forceinline__ void mma_f16(float* c, const u32* a, const u32* b) {
    asm volatile("mma.sync.aligned.m16n8k16.row.col.f32.f16.f16.f32 "
        "{%0,%1,%2,%3}, {%4,%5,%6,%7}, {%8,%9}, {%0,%1,%2,%3};"
        : "+f"(c[0]), "+f"(c[1]), "+f"(c[2]), "+f"(c[3])
        : "r"(a[0]), "r"(a[1]), "r"(a[2]), "r"(a[3]), "r"(b[0]), "r"(b[1]));
}

__device__ __forceinline__ u32 pack2(h16 a, h16 b) {
    return (u32)__half_as_ushort(a) | ((u32)__half_as_ushort(b) << 16);
}
__device__ __forceinline__ u32 pack2f(float a, float b) {
    return pack2(__float2half_rn(a), __float2half_rn(b));
}

// ===================================================================
// GEMM config: BM=BN=128, BK=32, 256 thr, 2Mx4N warps, warp tile 64x32.
// ===================================================================
#define G_ROWB  80u
#define G_B_OFF (128u * G_ROWB)
#define G_STG   (2u * 128u * G_ROWB)   // 20480 per stage

// ------------------- HMMA GEMM (generic) -------------------
// EPI: 0 none; 2 +biasN then GELU
// OUTM: 0 -> fp32 C; 1 -> fp16 Ch
// SPLITK: 1 -> blockIdx.z selects K-half; C offset by z*sCz; K = per-half K.
template<int EPI, int OUTM, int SPLITK>
__global__ __launch_bounds__(256, 2)
void gemm_mma(const h16* __restrict__ Ah, const h16* __restrict__ Bh,
              float* __restrict__ C, h16* __restrict__ Ch,
              int K, int lda, int ldb, int ldc,
              long long sCz,
              const float* __restrict__ biasN)
{
    extern __shared__ char smem[];
    const u32 sbase = smem_u32(smem);
    const int tid = threadIdx.x, lane = tid & 31, wid = tid >> 5;
    const int wm = wid & 1, wn = wid >> 1;     // 2 x 4

    if (SPLITK) {
        const int z = blockIdx.z;
        Ah += (size_t)z * K;
        Bh += (size_t)z * K;
        C  += (long long)z * sCz;
    }

    const int m0 = blockIdx.y * 128, n0 = blockIdx.x * 128;

    float acc[4][4][4];
    #pragma unroll
    for (int i = 0; i < 4; i++)
        #pragma unroll
        for (int j = 0; j < 4; j++)
            #pragma unroll
            for (int t = 0; t < 4; t++) acc[i][j][t] = 0.0f;

    auto load_chunk = [&](int ck, int st) {
        const int k0 = ck * 32;
        const u32 sa = sbase + (u32)st * G_STG;
        #pragma unroll
        for (int it = 0; it < 2; it++) {
            int a = tid + it * 256;
            int row = a >> 2, ch = a & 3;
            u32 dst = sa + (u32)row * G_ROWB + (u32)ch * 16;
            CP16(dst,           Ah + (size_t)(m0 + row) * lda + k0 + ch * 8);
            CP16(dst + G_B_OFF, Bh + (size_t)(n0 + row) * ldb + k0 + ch * 8);
        }
    };

    auto compute = [&](int st) {
        const u32 ab  = sbase + (u32)st * G_STG;
        const u32 bb  = ab + G_B_OFF;
        const u32 rb  = (u32)((lane & 15) * G_ROWB);
        #pragma unroll
        for (int s16 = 0; s16 < 2; s16++) {
            const u32 coff = (u32)(s16 * 32 + (lane >> 4) * 16);
            u32 bh[4][2];
            #pragma unroll
            for (int np = 0; np < 2; np++) {
                u32 bd = bb + (u32)((wn * 32 + np * 16) * G_ROWB) + rb + coff;
                u32 t0, t1, t2, t3;
                LDSM4(t0, t1, t2, t3, bd);
                bh[2*np][0] = t0; bh[2*np+1][0] = t1; bh[2*np][1] = t2; bh[2*np+1][1] = t3;
            }
            #pragma unroll
            for (int mt = 0; mt < 4; mt++) {
                u32 ah[4];
                u32 ad = ab + (u32)((wm * 64 + mt * 16) * G_ROWB) + rb + coff;
                LDSM4(ah[0], ah[1], ah[2], ah[3], ad);
                #pragma unroll
                for (int nt = 0; nt < 4; nt++)
                    mma_f16(acc[mt][nt], ah, bh[nt]);
            }
        }
    };

    const int NC = K >> 5;
    load_chunk(0, 0); CP_COMMIT();
    for (int i = 0; i < NC; i++) {
        CP_WAIT0();
        __syncthreads();
        if (i + 1 < NC) { load_chunk(i + 1, (i + 1) & 1); CP_COMMIT(); }
        compute(i & 1);
    }

    auto proc2 = [&](int gm, int gn, float v0, float v1) {
        if (EPI == 2) {
            float2 bn2 = *(const float2*)(biasN + gn);
            v0 += bn2.x; v1 += bn2.y;
            v0 = 0.5f * v0 * (1.0f + erff(v0 * 0.70710678118654752f));
            v1 = 0.5f * v1 * (1.0f + erff(v1 * 0.70710678118654752f));
        }
        if (OUTM == 0) {
            *(float2*)(C + (size_t)gm * ldc + gn) = make_float2(v0, v1);
        } else {
            *(u32*)(Ch + (size_t)gm * ldc + gn) = pack2f(v0, v1);
        }
    };

    const int r  = lane >> 2;
    const int c2 = (lane & 3) * 2;
    #pragma unroll
    for (int mt = 0; mt < 4; mt++) {
        #pragma unroll
        for (int nt = 0; nt < 4; nt++) {
            int gm = m0 + wm * 64 + mt * 16 + r;
            int gn = n0 + wn * 32 + nt * 8 + c2;
            proc2(gm,     gn, acc[mt][nt][0], acc[mt][nt][1]);
            proc2(gm + 8, gn, acc[mt][nt][2], acc[mt][nt][3]);
        }
    }
}

// ------------------- batched QKV GEMM (z selects matrix triple) -------------------
struct QKVArgs {
    const h16* Ah[3];
    const h16* Bh[3];
    h16* Ch[3];
};

__global__ __launch_bounds__(256, 2)
void gemm_qkv(QKVArgs args)
{
    extern __shared__ char smem[];
    const u32 sbase = smem_u32(smem);
    const int tid = threadIdx.x, lane = tid & 31, wid = tid >> 5;
    const int wm = wid & 1, wn = wid >> 1;
    const int zz = blockIdx.z;

    const h16* __restrict__ Ah = args.Ah[zz];
    const h16* __restrict__ Bh = args.Bh[zz];
    h16* __restrict__ Ch = args.Ch[zz];

    const int m0 = blockIdx.y * 128, n0 = blockIdx.x * 128;

    float acc[4][4][4];
    #pragma unroll
    for (int i = 0; i < 4; i++)
        #pragma unroll
        for (int j = 0; j < 4; j++)
            #pragma unroll
            for (int t = 0; t < 4; t++) acc[i][j][t] = 0.0f;

    auto load_chunk = [&](int ck, int st) {
        const int k0 = ck * 32;
        const u32 sa = sbase + (u32)st * G_STG;
        #pragma unroll
        for (int it = 0; it < 2; it++) {
            int a = tid + it * 256;
            int row = a >> 2, ch = a & 3;
            u32 dst = sa + (u32)row * G_ROWB + (u32)ch * 16;
            CP16(dst,           Ah + (size_t)(m0 + row) * DM + k0 + ch * 8);
            CP16(dst + G_B_OFF, Bh + (size_t)(n0 + row) * DM + k0 + ch * 8);
        }
    };

    auto compute = [&](int st) {
        const u32 ab  = sbase + (u32)st * G_STG;
        const u32 bb  = ab + G_B_OFF;
        const u32 rb  = (u32)((lane & 15) * G_ROWB);
        #pragma unroll
        for (int s16 = 0; s16 < 2; s16++) {
            const u32 coff = (u32)(s16 * 32 + (lane >> 4) * 16);
            u32 bh[4][2];
            #pragma unroll
            for (int np = 0; np < 2; np++) {
                u32 bd = bb + (u32)((wn * 32 + np * 16) * G_ROWB) + rb + coff;
                u32 t0, t1, t2, t3;
                LDSM4(t0, t1, t2, t3, bd);
                bh[2*np][0] = t0; bh[2*np+1][0] = t1; bh[2*np][1] = t2; bh[2*np+1][1] = t3;
            }
            #pragma unroll
            for (int mt = 0; mt < 4; mt++) {
                u32 ah[4];
                u32 ad = ab + (u32)((wm * 64 + mt * 16) * G_ROWB) + rb + coff;
                LDSM4(ah[0], ah[1], ah[2], ah[3], ad);
                #pragma unroll
                for (int nt = 0; nt < 4; nt++)
                    mma_f16(acc[mt][nt], ah, bh[nt]);
            }
        }
    };

    const int NC = DM >> 5;
    load_chunk(0, 0); CP_COMMIT();
    for (int i = 0; i < NC; i++) {
        CP_WAIT0();
        __syncthreads();
        if (i + 1 < NC) { load_chunk(i + 1, (i + 1) & 1); CP_COMMIT(); }
        compute(i & 1);
    }

    const int r  = lane >> 2;
    const int c2 = (lane & 3) * 2;
    #pragma unroll
    for (int mt = 0; mt < 4; mt++) {
        #pragma unroll
        for (int nt = 0; nt < 4; nt++) {
            int gm = m0 + wm * 64 + mt * 16 + r;
            int gn = n0 + wn * 32 + nt * 8 + c2;
            *(u32*)(Ch + (size_t)gm * DM + gn)       = pack2f(acc[mt][nt][0], acc[mt][nt][1]);
            *(u32*)(Ch + (size_t)(gm + 8) * DM + gn) = pack2f(acc[mt][nt][2], acc[mt][nt][3]);
        }
    }
}

// ------------------- fused flash attention (all single fp16) -------------------
__global__ __launch_bounds__(256, 2)
void flash_k(const h16* __restrict__ qg,
             const h16* __restrict__ kh, const h16* __restrict__ vh,
             const float* __restrict__ bias,
             h16* __restrict__ og)
{
    constexpr u32 ROWB = 144;
    constexpr u32 HKV  = 64 * ROWB;
    constexpr u32 STG  = 2 * HKV;

    extern __shared__ char smem[];
    const u32 sbase = smem_u32(smem);
    const int tid = threadIdx.x, lane = tid & 31, wid = tid >> 5;
    const int b = blockIdx.z, h = blockIdx.y, q0 = blockIdx.x * 128;

    const size_t qbase = ((size_t)b * SQ + q0) * DM + h * 64;
    const size_t kvbase = (size_t)b * SQ * DM + h * 64;
    const float* bptr = bias + ((size_t)(b * NHD + h)) * SQ * SQ;

    #pragma unroll
    for (int it = 0; it < 4; it++) {
        int idx = tid + it * 256;
        int row = idx >> 3, c8 = idx & 7;
        u32 dst = sbase + (u32)row * ROWB + (u32)c8 * 16;
        CP16(dst, qg + qbase + (size_t)row * DM + c8 * 8);
    }
    CP_COMMIT(); CP_WAIT0();
    __syncthreads();

    u32 qf[4][4];
    {
        const u32 base = sbase + (u32)((wid * 16 + (lane & 15)) * ROWB);
        #pragma unroll
        for (int kq = 0; kq < 4; kq++) {
            u32 ad = base + (u32)(kq * 32 + (lane >> 4) * 16);
            LDSM4(qf[kq][0], qf[kq][1], qf[kq][2], qf[kq][3], ad);
        }
    }
    __syncthreads();

    auto load_kv = [&](int ck, u32 st) {
        const int kv0 = ck * 64;
        #pragma unroll
        for (int it = 0; it < 2; it++) {
            int idx = tid + it * 256;
            int row = idx >> 3, c8 = idx & 7;
            size_t g = kvbase + (size_t)(kv0 + row) * DM + c8 * 8;
            u32 dst = st + (u32)row * ROWB + (u32)c8 * 16;
            CP16(dst,       kh + g);
            CP16(dst + HKV, vh + g);
        }
    };

    float o[8][4];
    #pragma unroll
    for (int d = 0; d < 8; d++)
        #pragma unroll
        for (int t = 0; t < 4; t++) o[d][t] = 0.0f;
    float rm0 = -1e30f, rm1 = -1e30f, rs0 = 0.0f, rs1 = 0.0f;

    load_kv(0, sbase); CP_COMMIT();

    const u32 rbA = (u32)((lane & 15) * ROWB);
    const int g4  = lane >> 2, t4 = lane & 3;

    for (int ck = 0; ck < SQ / 64; ck++) {
        const u32 st = sbase + (u32)(ck & 1) * STG;
        CP_WAIT0();
        __syncthreads();
        if (ck + 1 < SQ / 64) { load_kv(ck + 1, sbase + (u32)((ck + 1) & 1) * STG); CP_COMMIT(); }

        float S[8][4];
        #pragma unroll
        for (int j = 0; j < 8; j++)
            #pragma unroll
            for (int t = 0; t < 4; t++) S[j][t] = 0.0f;

        #pragma unroll
        for (int kq = 0; kq < 4; kq++) {
            const u32 coff = (u32)(kq * 32 + (lane >> 4) * 16);
            #pragma unroll
            for (int jp = 0; jp < 4; jp++) {
                u32 kd = st + (u32)(jp * 16 * ROWB) + rbA + coff;
                u32 t0, t1, t2, t3;
                u32 bh[2][2];
                LDSM4(t0, t1, t2, t3, kd);
                bh[0][0] = t0; bh[1][0] = t1; bh[0][1] = t2; bh[1][1] = t3;
                #pragma unroll
                for (int u = 0; u < 2; u++)
                    mma_f16(S[2*jp+u], qf[kq], bh[u]);
            }
        }

        const int kv0 = ck * 64;
        const int row0 = q0 + wid * 16 + g4;
        #pragma unroll
        for (int j = 0; j < 8; j++) {
            const int col = kv0 + j * 8 + t4 * 2;
            float2 bz0 = *(const float2*)(bptr + (size_t)row0 * SQ + col);
            float2 bz1 = *(const float2*)(bptr + (size_t)(row0 + 8) * SQ + col);
            S[j][0] = S[j][0] * 0.125f + bz0.x;
            S[j][1] = S[j][1] * 0.125f + bz0.y;
            S[j][2] = S[j][2] * 0.125f + bz1.x;
            S[j][3] = S[j][3] * 0.125f + bz1.y;
        }

        float m0 = -1e30f, m1 = -1e30f;
        #pragma unroll
        for (int j = 0; j < 8; j++) {
            m0 = fmaxf(m0, fmaxf(S[j][0], S[j][1]));
            m1 = fmaxf(m1, fmaxf(S[j][2], S[j][3]));
        }
        m0 = fmaxf(m0, __shfl_xor_sync(0xffffffffu, m0, 1));
        m0 = fmaxf(m0, __shfl_xor_sync(0xffffffffu, m0, 2));
        m1 = fmaxf(m1, __shfl_xor_sync(0xffffffffu, m1, 1));
        m1 = fmaxf(m1, __shfl_xor_sync(0xffffffffu, m1, 2));
        const float nm0 = fmaxf(rm0, m0), nm1 = fmaxf(rm1, m1);
        const float f0 = __expf(rm0 - nm0), f1 = __expf(rm1 - nm1);
        float ls0 = 0.0f, ls1 = 0.0f;
        #pragma unroll
        for (int j = 0; j < 8; j++) {
            S[j][0] = __expf(S[j][0] - nm0); ls0 += S[j][0];
            S[j][1] = __expf(S[j][1] - nm0); ls0 += S[j][1];
            S[j][2] = __expf(S[j][2] - nm1); ls1 += S[j][2];
            S[j][3] = __expf(S[j][3] - nm1); ls1 += S[j][3];
        }
        rs0 = rs0 * f0 + ls0;
        rs1 = rs1 * f1 + ls1;
        rm0 = nm0; rm1 = nm1;
        #pragma unroll
        for (int d = 0; d < 8; d++) {
            o[d][0] *= f0; o[d][1] *= f0; o[d][2] *= f1; o[d][3] *= f1;
        }

        u32 pa[4][4];
        #pragma unroll
        for (int kp = 0; kp < 4; kp++) {
            pa[kp][0] = pack2f(S[2*kp][0],   S[2*kp][1]);
            pa[kp][1] = pack2f(S[2*kp][2],   S[2*kp][3]);
            pa[kp][2] = pack2f(S[2*kp+1][0], S[2*kp+1][1]);
            pa[kp][3] = pack2f(S[2*kp+1][2], S[2*kp+1][3]);
        }

        const u32 vbase = st + HKV;
        const u32 vrow  = (u32)((lane & 7) + 8 * ((lane >> 3) & 1));
        const u32 vcolb = (u32)((lane >> 4) * 16);
        #pragma unroll
        for (int kp = 0; kp < 4; kp++) {
            #pragma unroll
            for (int dp = 0; dp < 4; dp++) {
                u32 vd = vbase + (u32)((kp * 16 + vrow) * ROWB) + (u32)(dp * 32) + vcolb;
                u32 r0, r1, r2, r3;
                u32 vhf[2][2];
                LDSM4T(r0, r1, r2, r3, vd);
                vhf[0][0] = r0; vhf[0][1] = r1; vhf[1][0] = r2; vhf[1][1] = r3;
                #pragma unroll
                for (int u = 0; u < 2; u++)
                    mma_f16(o[2*dp+u], pa[kp], vhf[u]);
            }
        }
    }

    rs0 += __shfl_xor_sync(0xffffffffu, rs0, 1);
    rs0 += __shfl_xor_sync(0xffffffffu, rs0, 2);
    rs1 += __shfl_xor_sync(0xffffffffu, rs1, 1);
    rs1 += __shfl_xor_sync(0xffffffffu, rs1, 2);
    const float i0 = 1.0f / rs0, i1 = 1.0f / rs1;
    const int row0 = q0 + wid * 16 + g4;
    #pragma unroll
    for (int d = 0; d < 8; d++) {
        const int col = h * 64 + d * 8 + t4 * 2;
        *(u32*)(og + ((size_t)b * SQ + row0) * DM + col)     = pack2f(o[d][0] * i0, o[d][1] * i0);
        *(u32*)(og + ((size_t)b * SQ + row0 + 8) * DM + col) = pack2f(o[d][2] * i1, o[d][3] * i1);
    }
}

// ------------------- merged convert fp32 -> fp16 -------------------
struct SplitTab {
    const float* x[8];
    h16* h[8];
    int endblk[8];
};

__global__ __launch_bounds__(256)
void splitall_k(SplitTab t)
{
    int bk = blockIdx.x;
    int r = 0;
    #pragma unroll
    for (int j = 0; j < 8; j++) if (bk >= t.endblk[j]) r = j + 1;
    int start = r ? t.endblk[r - 1] : 0;
    size_t i = (size_t)(bk - start) * 256 + threadIdx.x;
    float4 v = ((const float4*)t.x[r])[i];
    ((uint2*)t.h[r])[i] = make_uint2(pack2f(v.x, v.y), pack2f(v.z, v.w));
}

// ------------------- combine split-K partials + residual (+bias) + LayerNorm ----
// MODE 1: v = p0+p1+res            -> write x1out (fp32) and ln fp16
// MODE 2: v = p0+p1+res+biasN     -> write out fp32 (final LN)
template<int MODE>
__global__ __launch_bounds__(256)
void ln_comb_k(const float* __restrict__ part, const float* __restrict__ res,
               const float* __restrict__ biasN,
               float* __restrict__ x1out, h16* __restrict__ lnout,
               float* __restrict__ out,
               const float* __restrict__ gg, const float* __restrict__ bb)
{
    const size_t rowoff = (size_t)blockIdx.x * DM;
    const int tid = threadIdx.x, lane = tid & 31, warp = tid >> 5;
    __shared__ float r1[8], r2[8];

    float4 p0 = ((const float4*)(part + rowoff))[tid];
    float4 p1 = ((const float4*)(part + (size_t)MR * DM + rowoff))[tid];
    float4 rr = ((const float4*)(res + rowoff))[tid];
    float v[4] = {p0.x + p1.x + rr.x, p0.y + p1.y + rr.y,
                  p0.z + p1.z + rr.z, p0.w + p1.w + rr.w};
    if (MODE == 2) {
        float4 b4 = ((const float4*)biasN)[tid];
        v[0] += b4.x; v[1] += b4.y; v[2] += b4.z; v[3] += b4.w;
    }
    if (MODE == 1)
        ((float4*)(x1out + rowoff))[tid] = make_float4(v[0], v[1], v[2], v[3]);

    float sm = v[0]+v[1]+v[2]+v[3];
    float s2 = v[0]*v[0]+v[1]*v[1]+v[2]*v[2]+v[3]*v[3];
    #pragma unroll
    for (int o = 16; o; o >>= 1) {
        sm += __shfl_xor_sync(0xffffffffu, sm, o);
        s2 += __shfl_xor_sync(0xffffffffu, s2, o);
    }
    if (!lane) { r1[warp] = sm; r2[warp] = s2; }
    __syncthreads();
    sm = 0.0f; s2 = 0.0f;
    #pragma unroll
    for (int i = 0; i < 8; i++) { sm += r1[i]; s2 += r2[i]; }
    const float mean = sm * (1.0f / DM);
    const float var  = s2 * (1.0f / DM) - mean * mean;
    const float inv  = rsqrtf(var + 1e-5f);

    float4 g4 = ((const float4*)gg)[tid];
    float4 b4 = ((const float4*)bb)[tid];
    float o0 = (v[0]-mean)*inv*g4.x + b4.x;
    float o1 = (v[1]-mean)*inv*g4.y + b4.y;
    float o2 = (v[2]-mean)*inv*g4.z + b4.z;
    float o3 = (v[3]-mean)*inv*g4.w + b4.w;
    if (MODE == 1) {
        ((uint2*)(lnout + rowoff))[tid] = make_uint2(pack2f(o0,o1), pack2f(o2,o3));
    } else {
        ((float4*)(out + rowoff))[tid] = make_float4(o0,o1,o2,o3);
    }
}

// ------------------- launch -------------------
#define SMEM_GEMM (2 * 2 * 128 * 80)    // 40960
#define SMEM_FLASH (2 * 2 * 64 * 144)   // 36864

extern "C" void kernel_launch(void* const* d_in, const int* in_sizes, int n_in,
                              void* d_out, int out_size)
{
    const float* x_q  = (const float*)d_in[0];
    const float* x_kv = (const float*)d_in[1];
    const float* bias = (const float*)d_in[2];
    const float* Wq   = (const float*)d_in[3];
    const float* Wk   = (const float*)d_in[4];
    const float* Wv   = (const float*)d_in[5];
    const float* Wo   = (const float*)d_in[6];
    const float* W1   = (const float*)d_in[7];
    const float* b1   = (const float*)d_in[8];
    const float* W2   = (const float*)d_in[9];
    const float* b2   = (const float*)d_in[10];
    const float* g1   = (const float*)d_in[11];
    const float* be1  = (const float*)d_in[12];
    const float* g2   = (const float*)d_in[13];
    const float* be2  = (const float*)d_in[14];
    float* out = (float*)d_out;

    h16 *xq,*xk,*wq,*wk,*wv,*wo,*w1,*w2;
    h16 *q,*k,*v,*o,*ln,*hh;
    float *x1,*part;
    cudaGetSymbolAddress((void**)&xq, s_xq);
    cudaGetSymbolAddress((void**)&xk, s_xk);
    cudaGetSymbolAddress((void**)&wq, s_wq);
    cudaGetSymbolAddress((void**)&wk, s_wk);
    cudaGetSymbolAddress((void**)&wv, s_wv);
    cudaGetSymbolAddress((void**)&wo, s_wo);
    cudaGetSymbolAddress((void**)&w1, s_w1);
    cudaGetSymbolAddress((void**)&w2, s_w2);
    cudaGetSymbolAddress((void**)&q,  s_q);
    cudaGetSymbolAddress((void**)&k,  s_k);
    cudaGetSymbolAddress((void**)&v,  s_v);
    cudaGetSymbolAddress((void**)&o,  s_o);
    cudaGetSymbolAddress((void**)&x1, s_x1);
    cudaGetSymbolAddress((void**)&ln, s_ln);
    cudaGetSymbolAddress((void**)&hh, s_h);
    cudaGetSymbolAddress((void**)&part, s_part);

    cudaFuncSetAttribute(gemm_mma<0,0,1>, cudaFuncAttributeMaxDynamicSharedMemorySize, SMEM_GEMM);
    cudaFuncSetAttribute(gemm_mma<2,1,0>, cudaFuncAttributeMaxDynamicSharedMemorySize, SMEM_GEMM);
    cudaFuncSetAttribute(gemm_qkv,        cudaFuncAttributeMaxDynamicSharedMemorySize, SMEM_GEMM);
    cudaFuncSetAttribute(flash_k,         cudaFuncAttributeMaxDynamicSharedMemorySize, SMEM_FLASH);

    // one merged conversion launch: everything to single fp16
    {
        SplitTab t;
        t.x[0]=x_q;  t.h[0]=xq;
        t.x[1]=x_kv; t.h[1]=xk;
        t.x[2]=Wq;   t.h[2]=wq;
        t.x[3]=Wk;   t.h[3]=wk;
        t.x[4]=Wv;   t.h[4]=wv;
        t.x[5]=Wo;   t.h[5]=wo;
        t.x[6]=W1;   t.h[6]=w1;
        t.x[7]=W2;   t.h[7]=w2;
        int blks[8] = {MR*DM/1024, MR*DM/1024, DM*DM/1024, DM*DM/1024,
                       DM*DM/1024, DM*DM/1024, FF*DM/1024, DM*FF/1024};
        int acc_ = 0;
        for (int j = 0; j < 8; j++) { acc_ += blks[j]; t.endblk[j] = acc_; }
        splitall_k<<<acc_, 256>>>(t);
    }

    // Q, K, V projections in ONE batched launch
    {
        QKVArgs a;
        a.Ah[0]=xq; a.Bh[0]=wq; a.Ch[0]=q;
        a.Ah[1]=xk; a.Bh[1]=wk; a.Ch[1]=k;
        a.Ah[2]=xk; a.Bh[2]=wv; a.Ch[2]=v;
        gemm_qkv<<<dim3(DM/128, MR/128, 3), 256, SMEM_GEMM>>>(a);
    }

    // fused attention
    flash_k<<<dim3(SQ/128, NHD, BB), 256, SMEM_FLASH>>>(q, k, v, bias, o);

    // O @ Wo^T with split-K=2 -> partials, then combine+residual+LN1
    gemm_mma<0,0,1><<<dim3(DM/128, MR/128, 2), 256, SMEM_GEMM>>>(
        o, wo, part, nullptr,
        DM/2, DM, DM, DM, (long long)MR * DM, nullptr);
    ln_comb_k<1><<<MR, 256>>>(part, x_q, nullptr, x1, ln, nullptr, g1, be1);

    // h = gelu(ln1 @ W1^T + b1)
    gemm_mma<2,1,0><<<dim3(FF/128, MR/128, 1), 256, SMEM_GEMM>>>(
        ln, w1, nullptr, hh,
        DM, DM, DM, FF, 0, b1);

    // h @ W2^T with split-K=2 -> partials, then combine+x1+b2+LN2 -> out
    gemm_mma<0,0,1><<<dim3(DM/128, MR/128, 2), 256, SMEM_GEMM>>>(
        hh, w2, part, nullptr,
        FF/2, FF, FF, DM, (long long)MR * DM, nullptr);
    ln_comb_k<2><<<MR, 256>>>(part, x1, b2, nullptr, nullptr, out, g2, be2);
}